// round 6
// baseline (speedup 1.0000x reference)
#include <cuda_runtime.h>
#include <math.h>

#define HID   2048
#define NHEAD 16
#define HD    128
#define NBATCH 8
#define SEQ   128
#define CTX   4096
#define ANC   4
#define SL    4100            // attention key length (4 anchors + 4096 cache)
#define MROWS 1028            // 1024 x-rows + 4 anchor rows
#define NJT   129             // ceil(4100/32) j-tiles in flash attention

// ---------------- tf32 mma helpers ----------------
__device__ __forceinline__ unsigned f2tf(float f) {
    unsigned r;
    asm("cvt.rna.tf32.f32 %0, %1;" : "=r"(r) : "f"(f));
    return r;
}
__device__ __forceinline__ void mma_tf32(float c[4],
                                         unsigned a0, unsigned a1, unsigned a2, unsigned a3,
                                         unsigned b0, unsigned b1) {
    asm volatile(
        "mma.sync.aligned.m16n8k8.row.col.f32.tf32.tf32.f32 "
        "{%0,%1,%2,%3}, {%4,%5,%6,%7}, {%8,%9}, {%0,%1,%2,%3};\n"
        : "+f"(c[0]), "+f"(c[1]), "+f"(c[2]), "+f"(c[3])
        : "r"(a0), "r"(a1), "r"(a2), "r"(a3), "r"(b0), "r"(b1));
}

// ---------------- device scratch ----------------
__device__ float  g_Qp[(size_t)MROWS * HID];
__device__ float  g_Kp[(size_t)MROWS * HID];
__device__ float  g_Vp[(size_t)MROWS * HID];
__device__ float  g_Qr[(size_t)128 * 128 * 128];   // [bh][s][d], rope'd + scaled
__device__ float  g_AO[(size_t)1024 * HID];        // attention output
__device__ float2 g_cs[(size_t)SL * 64];           // (cos,sin); d and d+64 share

// ---------------- RoPE cos/sin table ----------------
__global__ void rope_table_kernel() {
    int idx = blockIdx.x * blockDim.x + threadIdx.x;
    if (idx >= SL * 64) return;
    int pos = idx >> 6;
    int i   = idx & 63;
    double invd = 1.0 / pow(10000.0, (double)i / 64.0);
    float  invf = (float)invd;
    float  ang  = (float)pos * invf;      // fp32 rounding, matches reference
    g_cs[idx] = make_float2((float)cos((double)ang), (float)sin((double)ang));
}

// ---------------- pipelined tf32 NT GEMM: C[m,n] = sum_k A[m,k] * W[n,k] --------
template<int BN, int TU>
__global__ void __launch_bounds__(256, 1) gemm_tf32(
    const float* __restrict__ A0, const float* __restrict__ A1, int split, int M,
    const float* __restrict__ W0, const float* __restrict__ W1, const float* __restrict__ W2,
    float* __restrict__ C0, float* __restrict__ C1, float* __restrict__ C2)
{
    const float* Bw = (blockIdx.z == 0) ? W0 : (blockIdx.z == 1) ? W1 : W2;
    float*       C  = (blockIdx.z == 0) ? C0 : (blockIdx.z == 1) ? C1 : C2;
    const int m0 = blockIdx.y * 128;
    const int n0 = blockIdx.x * BN;

    extern __shared__ unsigned smg[];
    const int ASTR = 132, BSTR = BN + 4;
    const int BOFF = 2 * 32 * ASTR;
#define ASG(bf, k, m) smg[((bf) * 32 + (k)) * ASTR + (m)]
#define BSG(bf, k, n) smg[BOFF + ((bf) * 32 + (k)) * BSTR + (n)]

    const int tid  = threadIdx.x;
    const int wid  = tid >> 5;
    const int lane = tid & 31;
    const int g    = lane >> 2;
    const int tg   = lane & 3;
    const int wm   = (wid >> 2) * 64;
    const int wn   = (wid & 3) * (8 * TU);

    const int am  = tid >> 1;
    const int ak4 = (tid & 1) * 4;
    constexpr int TPR  = 256 / BN;
    constexpr int F4PT = 8 / TPR;
    const int bn  = tid / TPR;
    const int bk4 = (tid % TPR) * F4PT;

    const bool avalid = (m0 + am) < M;
    const float* asrc = avalid
        ? ((m0 + am < split) ? A0 + (size_t)(m0 + am) * HID
                             : A1 + (size_t)(m0 + am - split) * HID)
        : A0;
    const float* bsrc = Bw + (size_t)(n0 + bn) * HID;

    float acc[4][TU][4];
#pragma unroll
    for (int t = 0; t < 4; t++)
#pragma unroll
        for (int u = 0; u < TU; u++)
#pragma unroll
            for (int c = 0; c < 4; c++) acc[t][u][c] = 0.f;

    float4 pa[4], pb[F4PT];

#pragma unroll
    for (int q = 0; q < 4; q++)
        pa[q] = avalid ? *(const float4*)(asrc + (ak4 + q) * 4)
                       : make_float4(0.f, 0.f, 0.f, 0.f);
#pragma unroll
    for (int q = 0; q < F4PT; q++)
        pb[q] = *(const float4*)(bsrc + (bk4 + q) * 4);
#pragma unroll
    for (int q = 0; q < 4; q++) {
        int k = (ak4 + q) * 4;
        ASG(0, k + 0, am) = f2tf(pa[q].x); ASG(0, k + 1, am) = f2tf(pa[q].y);
        ASG(0, k + 2, am) = f2tf(pa[q].z); ASG(0, k + 3, am) = f2tf(pa[q].w);
    }
#pragma unroll
    for (int q = 0; q < F4PT; q++) {
        int k = (bk4 + q) * 4;
        BSG(0, k + 0, bn) = f2tf(pb[q].x); BSG(0, k + 1, bn) = f2tf(pb[q].y);
        BSG(0, k + 2, bn) = f2tf(pb[q].z); BSG(0, k + 3, bn) = f2tf(pb[q].w);
    }
    __syncthreads();

    const int NK = HID / 32;
    for (int t = 0; t < NK; t++) {
        const int cur  = t & 1;
        const bool more = (t + 1 < NK);
        if (more) {
            const int k0 = (t + 1) * 32;
#pragma unroll
            for (int q = 0; q < 4; q++)
                pa[q] = avalid ? *(const float4*)(asrc + k0 + (ak4 + q) * 4)
                               : make_float4(0.f, 0.f, 0.f, 0.f);
#pragma unroll
            for (int q = 0; q < F4PT; q++)
                pb[q] = *(const float4*)(bsrc + k0 + (bk4 + q) * 4);
        }
#pragma unroll
        for (int k8 = 0; k8 < 4; k8++) {
            unsigned a[4][4];
#pragma unroll
            for (int tt = 0; tt < 4; tt++) {
                a[tt][0] = ASG(cur, k8 * 8 + tg,     wm + 16 * tt + g);
                a[tt][1] = ASG(cur, k8 * 8 + tg,     wm + 16 * tt + g + 8);
                a[tt][2] = ASG(cur, k8 * 8 + tg + 4, wm + 16 * tt + g);
                a[tt][3] = ASG(cur, k8 * 8 + tg + 4, wm + 16 * tt + g + 8);
            }
            unsigned b[TU][2];
#pragma unroll
            for (int u = 0; u < TU; u++) {
                b[u][0] = BSG(cur, k8 * 8 + tg,     wn + 8 * u + g);
                b[u][1] = BSG(cur, k8 * 8 + tg + 4, wn + 8 * u + g);
            }
#pragma unroll
            for (int tt = 0; tt < 4; tt++)
#pragma unroll
                for (int u = 0; u < TU; u++)
                    mma_tf32(acc[tt][u], a[tt][0], a[tt][1], a[tt][2], a[tt][3],
                             b[u][0], b[u][1]);
        }
        if (more) {
            const int nxt = cur ^ 1;
#pragma unroll
            for (int q = 0; q < 4; q++) {
                int k = (ak4 + q) * 4;
                ASG(nxt, k + 0, am) = f2tf(pa[q].x); ASG(nxt, k + 1, am) = f2tf(pa[q].y);
                ASG(nxt, k + 2, am) = f2tf(pa[q].z); ASG(nxt, k + 3, am) = f2tf(pa[q].w);
            }
#pragma unroll
            for (int q = 0; q < F4PT; q++) {
                int k = (bk4 + q) * 4;
                BSG(nxt, k + 0, bn) = f2tf(pb[q].x); BSG(nxt, k + 1, bn) = f2tf(pb[q].y);
                BSG(nxt, k + 2, bn) = f2tf(pb[q].z); BSG(nxt, k + 3, bn) = f2tf(pb[q].w);
            }
            __syncthreads();
        }
    }

#pragma unroll
    for (int tt = 0; tt < 4; tt++) {
        int r0 = m0 + wm + 16 * tt + g;
        int r1 = r0 + 8;
#pragma unroll
        for (int u = 0; u < TU; u++) {
            int n = n0 + wn + 8 * u + 2 * tg;
            if (r0 < M) *(float2*)(C + (size_t)r0 * HID + n) = make_float2(acc[tt][u][0], acc[tt][u][1]);
            if (r1 < M) *(float2*)(C + (size_t)r1 * HID + n) = make_float2(acc[tt][u][2], acc[tt][u][3]);
        }
    }
#undef ASG
#undef BSG
}

#define GEMM_SMEM_256 ((2 * 32 * 132 + 2 * 32 * 260) * 4)
#define GEMM_SMEM_128 ((2 * 32 * 132 + 2 * 32 * 132) * 4)

// ---------------- RoPE on Q (also folds 1/sqrt(HD)) ----------------
__global__ void rope_q_kernel(const float* __restrict__ Qp, float* __restrict__ Qr) {
    int idx = blockIdx.x * blockDim.x + threadIdx.x;
    if (idx >= 128 * 128 * 128) return;
    int d  = idx & 127;
    int s  = (idx >> 7) & 127;
    int bh = idx >> 14;
    int b = bh >> 4, h = bh & 15;
    const float* src = Qp + (size_t)(b * 128 + s) * HID + h * 128;
    float v = src[d];
    float p = (d < 64) ? -src[d + 64] : src[d - 64];
    int pos = s + ANC;
    float2 cs = g_cs[pos * 64 + (d & 63)];
    Qr[idx] = (v * cs.x + p * cs.y) * 0.08838834764831845f;
}

// ---------------- fused flash attention (q-split, 2 CTAs per head) -------------
// grid = 256 blocks: blockIdx.x = bh*2 + qhalf. 128 threads = 4 warps,
// warp w owns q rows qhalf*64 + 16w .. +15. 2 CTAs co-resident per SM.
// smem words: KS 128x36 @0 | VS 32x132 @4608 | PS 4x576 @8832  (total 11136)
#define KS(d, j)     sm[(d) * 36 + (j)]
#define VS(j, d)     sm[4608 + (j) * 132 + (d)]
#define PS(w, j, q)  sm[8832 + (w) * 576 + (j) * 18 + (q)]
#define FLASH_SMEM   (11136 * 4)

__global__ void __launch_bounds__(128, 2) flash_attn(
    const float* __restrict__ Qr, const float* __restrict__ Kp,
    const float* __restrict__ Vp, const float* __restrict__ past_k,
    const float* __restrict__ past_v,
    float* __restrict__ kcache, float* __restrict__ vcache,
    float* __restrict__ AO)
{
    extern __shared__ unsigned sm[];
    const int bh    = blockIdx.x >> 1;
    const int qhalf = blockIdx.x & 1;
    const int b = bh >> 4, h = bh & 15;
    const int tid  = threadIdx.x;
    const int w    = tid >> 5;
    const int lane = tid & 31;
    const int g    = lane >> 2;
    const int tg   = lane & 3;
    const int qb   = qhalf * 64 + 16 * w;

    // staging mapping: 4 threads per row, 16+16 d-values each
    const int jj = tid >> 2;           // 0..31
    const int c0 = (tid & 3) * 16;     // 0,16,32,48

    // Q fragments in registers for the whole kernel
    unsigned qa[16][4];
    {
        const float* q = Qr + (size_t)bh * 128 * 128;
#pragma unroll
        for (int kk = 0; kk < 16; kk++) {
            int d = 8 * kk + tg;
            qa[kk][0] = f2tf(q[(qb + g    ) * 128 + d    ]);
            qa[kk][1] = f2tf(q[(qb + g + 8) * 128 + d    ]);
            qa[kk][2] = f2tf(q[(qb + g    ) * 128 + d + 4]);
            qa[kk][3] = f2tf(q[(qb + g + 8) * 128 + d + 4]);
        }
    }

    float Oacc[16][4];
#pragma unroll
    for (int nt = 0; nt < 16; nt++)
#pragma unroll
        for (int c = 0; c < 4; c++) Oacc[nt][c] = 0.f;
    float mrow[2] = {-1e30f, -1e30f};
    float lrow[2] = {0.f, 0.f};

    for (int jt = 0; jt < NJT; jt++) {
        const int j0 = jt * 32;
        const int jg = j0 + jj;

        // ---- stage K (rope'd) and V; qhalf 0 writes raw rows to cache outputs ----
        if (jg < SL) {
            const float *ksrc, *vsrc;
            bool cw = false;
            size_t cbase = 0;
            if (jg < ANC) {
                ksrc = Kp + (size_t)(1024 + jg) * HID + h * 128;
                vsrc = Vp + (size_t)(1024 + jg) * HID + h * 128;
            } else {
                int cr = jg - ANC;
                cbase = ((size_t)bh * CTX + cr) * 128;
                cw = (qhalf == 0);
                if (cr < CTX - SEQ) {
                    ksrc = past_k + ((size_t)bh * CTX + cr + SEQ) * 128;
                    vsrc = past_v + ((size_t)bh * CTX + cr + SEQ) * 128;
                } else {
                    int ss = cr - (CTX - SEQ);
                    ksrc = Kp + (size_t)(b * SEQ + ss) * HID + h * 128;
                    vsrc = Vp + (size_t)(b * SEQ + ss) * HID + h * 128;
                }
            }
            const float2* csp = g_cs + (size_t)jg * 64 + c0;
            float kl[16], kh[16], vl[16], vh[16];
#pragma unroll
            for (int q4 = 0; q4 < 4; q4++) {
                *(float4*)(kl + 4 * q4) = *(const float4*)(ksrc + c0 + 4 * q4);
                *(float4*)(kh + 4 * q4) = *(const float4*)(ksrc + c0 + 64 + 4 * q4);
                *(float4*)(vl + 4 * q4) = *(const float4*)(vsrc + c0 + 4 * q4);
                *(float4*)(vh + 4 * q4) = *(const float4*)(vsrc + c0 + 64 + 4 * q4);
            }
            if (cw) {
#pragma unroll
                for (int q4 = 0; q4 < 4; q4++) {
                    *(float4*)(kcache + cbase + c0 + 4 * q4)      = *(float4*)(kl + 4 * q4);
                    *(float4*)(kcache + cbase + c0 + 64 + 4 * q4) = *(float4*)(kh + 4 * q4);
                    *(float4*)(vcache + cbase + c0 + 4 * q4)      = *(float4*)(vl + 4 * q4);
                    *(float4*)(vcache + cbase + c0 + 64 + 4 * q4) = *(float4*)(vh + 4 * q4);
                }
            }
#pragma unroll
            for (int u = 0; u < 16; u++) {
                float2 cs = csp[u];
                KS(c0 + u,      jj) = f2tf(kl[u] * cs.x - kh[u] * cs.y);
                KS(c0 + 64 + u, jj) = f2tf(kh[u] * cs.x + kl[u] * cs.y);
                VS(jj, c0 + u)      = f2tf(vl[u]);
                VS(jj, c0 + 64 + u) = f2tf(vh[u]);
            }
        } else {
#pragma unroll
            for (int u = 0; u < 16; u++) {
                KS(c0 + u, jj) = 0u; KS(c0 + 64 + u, jj) = 0u;
                VS(jj, c0 + u) = 0u; VS(jj, c0 + 64 + u) = 0u;
            }
        }
        __syncthreads();

        // ---- S = Q K^T ----
        float s[4][4];
#pragma unroll
        for (int u = 0; u < 4; u++)
#pragma unroll
            for (int c = 0; c < 4; c++) s[u][c] = 0.f;
#pragma unroll
        for (int kk = 0; kk < 16; kk++) {
#pragma unroll
            for (int u = 0; u < 4; u++) {
                unsigned b0 = KS(8 * kk + tg,     8 * u + g);
                unsigned b1 = KS(8 * kk + tg + 4, 8 * u + g);
                mma_tf32(s[u], qa[kk][0], qa[kk][1], qa[kk][2], qa[kk][3], b0, b1);
            }
        }

        // ---- mask tail + online softmax ----
#pragma unroll
        for (int u = 0; u < 4; u++) {
            int jl = 8 * u + 2 * tg;
            if (j0 + jl     >= SL) { s[u][0] = -1e30f; s[u][2] = -1e30f; }
            if (j0 + jl + 1 >= SL) { s[u][1] = -1e30f; s[u][3] = -1e30f; }
        }
        float tmax0 = -1e30f, tmax1 = -1e30f;
#pragma unroll
        for (int u = 0; u < 4; u++) {
            tmax0 = fmaxf(tmax0, fmaxf(s[u][0], s[u][1]));
            tmax1 = fmaxf(tmax1, fmaxf(s[u][2], s[u][3]));
        }
        tmax0 = fmaxf(tmax0, __shfl_xor_sync(0xffffffff, tmax0, 1));
        tmax0 = fmaxf(tmax0, __shfl_xor_sync(0xffffffff, tmax0, 2));
        tmax1 = fmaxf(tmax1, __shfl_xor_sync(0xffffffff, tmax1, 1));
        tmax1 = fmaxf(tmax1, __shfl_xor_sync(0xffffffff, tmax1, 2));
        float mn0 = fmaxf(mrow[0], tmax0);
        float mn1 = fmaxf(mrow[1], tmax1);
        float al0 = __expf(mrow[0] - mn0);
        float al1 = __expf(mrow[1] - mn1);
        mrow[0] = mn0; mrow[1] = mn1;

        float rs0 = 0.f, rs1 = 0.f;
#pragma unroll
        for (int u = 0; u < 4; u++) {
            s[u][0] = __expf(s[u][0] - mn0);
            s[u][1] = __expf(s[u][1] - mn0);
            s[u][2] = __expf(s[u][2] - mn1);
            s[u][3] = __expf(s[u][3] - mn1);
            rs0 += s[u][0] + s[u][1];
            rs1 += s[u][2] + s[u][3];
        }
        rs0 += __shfl_xor_sync(0xffffffff, rs0, 1);
        rs0 += __shfl_xor_sync(0xffffffff, rs0, 2);
        rs1 += __shfl_xor_sync(0xffffffff, rs1, 1);
        rs1 += __shfl_xor_sync(0xffffffff, rs1, 2);
        lrow[0] = lrow[0] * al0 + rs0;
        lrow[1] = lrow[1] * al1 + rs1;

#pragma unroll
        for (int nt = 0; nt < 16; nt++) {
            Oacc[nt][0] *= al0; Oacc[nt][1] *= al0;
            Oacc[nt][2] *= al1; Oacc[nt][3] *= al1;
        }

        // ---- P -> smem (per-warp) ----
#pragma unroll
        for (int u = 0; u < 4; u++) {
            int jl = 8 * u + 2 * tg;
            PS(w, jl,     g    ) = f2tf(s[u][0]);
            PS(w, jl + 1, g    ) = f2tf(s[u][1]);
            PS(w, jl,     g + 8) = f2tf(s[u][2]);
            PS(w, jl + 1, g + 8) = f2tf(s[u][3]);
        }
        __syncwarp();

        // ---- O += P V ----
#pragma unroll
        for (int kk = 0; kk < 4; kk++) {
            unsigned a0 = PS(w, 8 * kk + tg,     g);
            unsigned a1 = PS(w, 8 * kk + tg,     g + 8);
            unsigned a2 = PS(w, 8 * kk + tg + 4, g);
            unsigned a3 = PS(w, 8 * kk + tg + 4, g + 8);
#pragma unroll
            for (int nt = 0; nt < 16; nt++) {
                unsigned b0 = VS(8 * kk + tg,     8 * nt + g);
                unsigned b1 = VS(8 * kk + tg + 4, 8 * nt + g);
                mma_tf32(Oacc[nt], a0, a1, a2, a3, b0, b1);
            }
        }
        __syncthreads();
    }

    // ---- epilogue ----
    float inv0 = 1.0f / lrow[0];
    float inv1 = 1.0f / lrow[1];
    int r0 = b * 128 + qb + g;
    int r1 = r0 + 8;
#pragma unroll
    for (int nt = 0; nt < 16; nt++) {
        int d = h * 128 + 8 * nt + 2 * tg;
        *(float2*)(AO + (size_t)r0 * HID + d) = make_float2(Oacc[nt][0] * inv0, Oacc[nt][1] * inv0);
        *(float2*)(AO + (size_t)r1 * HID + d) = make_float2(Oacc[nt][2] * inv1, Oacc[nt][3] * inv1);
    }
}

// ---------------- launch ----------------
extern "C" void kernel_launch(void* const* d_in, const int* in_sizes, int n_in,
                              void* d_out, int out_size)
{
    const float* x      = (const float*)d_in[0];
    const float* past_k = (const float*)d_in[2];
    const float* past_v = (const float*)d_in[3];
    const float* anchor = (const float*)d_in[4];
    const float* Wq     = (const float*)d_in[5];
    const float* Wk     = (const float*)d_in[6];
    const float* Wv     = (const float*)d_in[7];
    const float* Wo     = (const float*)d_in[8];

    float* out    = (float*)d_out;
    float* kcache = out + (size_t)NBATCH * SEQ * HID;
    float* vcache = kcache + (size_t)NBATCH * NHEAD * CTX * HD;

    float *Qp, *Kp, *Vp, *Qr, *AO;
    cudaGetSymbolAddress((void**)&Qp, g_Qp);
    cudaGetSymbolAddress((void**)&Kp, g_Kp);
    cudaGetSymbolAddress((void**)&Vp, g_Vp);
    cudaGetSymbolAddress((void**)&Qr, g_Qr);
    cudaGetSymbolAddress((void**)&AO, g_AO);

    cudaFuncSetAttribute(gemm_tf32<256, 8>, cudaFuncAttributeMaxDynamicSharedMemorySize,
                         GEMM_SMEM_256);
    cudaFuncSetAttribute(gemm_tf32<128, 4>, cudaFuncAttributeMaxDynamicSharedMemorySize,
                         GEMM_SMEM_128);
    cudaFuncSetAttribute(flash_attn, cudaFuncAttributeMaxDynamicSharedMemorySize,
                         FLASH_SMEM);

    // 1) QKV projections
    gemm_tf32<256, 8><<<dim3(8, 9, 3), 256, GEMM_SMEM_256>>>(
        x, anchor, 1024, MROWS, Wq, Wk, Wv, Qp, Kp, Vp);

    // 2) RoPE table + Q rope
    rope_table_kernel<<<(SL * 64 + 255) / 256, 256>>>();
    rope_q_kernel<<<(128 * 128 * 128) / 256, 256>>>(Qp, Qr);

    // 3) fused attention (q-split 2 CTAs/head; qhalf 0 assembles caches)
    flash_attn<<<256, 128, FLASH_SMEM>>>(Qr, Kp, Vp, past_k, past_v,
                                         kcache, vcache, AO);

    // 4) output projection
    gemm_tf32<128, 4><<<dim3(16, 8, 1), 256, GEMM_SMEM_128>>>(
        AO, AO, 1024, 1024, Wo, Wo, Wo, out, out, out);
}

// round 7
// speedup vs baseline: 1.3256x; 1.3256x over previous
#include <cuda_runtime.h>
#include <math.h>

#define HID   2048
#define NHEAD 16
#define HD    128
#define NBATCH 8
#define SEQ   128
#define CTX   4096
#define ANC   4
#define SL    4100            // attention key length (4 anchors + 4096 cache)
#define MROWS 1028            // 1024 x-rows + 4 anchor rows
#define NJT   129             // ceil(4100/32) j-tiles in flash attention

// ---------------- tf32 mma helpers ----------------
__device__ __forceinline__ unsigned f2tf(float f) {
    unsigned r;
    asm("cvt.rna.tf32.f32 %0, %1;" : "=r"(r) : "f"(f));
    return r;
}
__device__ __forceinline__ void mma_tf32(float c[4],
                                         unsigned a0, unsigned a1, unsigned a2, unsigned a3,
                                         unsigned b0, unsigned b1) {
    asm volatile(
        "mma.sync.aligned.m16n8k8.row.col.f32.tf32.tf32.f32 "
        "{%0,%1,%2,%3}, {%4,%5,%6,%7}, {%8,%9}, {%0,%1,%2,%3};\n"
        : "+f"(c[0]), "+f"(c[1]), "+f"(c[2]), "+f"(c[3])
        : "r"(a0), "r"(a1), "r"(a2), "r"(a3), "r"(b0), "r"(b1));
}

// ---------------- device scratch ----------------
__device__ float  g_Qp[(size_t)MROWS * HID];
__device__ float  g_Kp[(size_t)MROWS * HID];
__device__ float  g_Vp[(size_t)MROWS * HID];
__device__ float  g_Qr[(size_t)128 * 128 * 128];   // [bh][s][d], rope'd + scaled
__device__ float  g_AO[(size_t)1024 * HID];        // attention output
__device__ float2 g_cs[(size_t)SL * 64];           // (cos,sin); d and d+64 share

// ---------------- RoPE cos/sin table ----------------
__global__ void rope_table_kernel() {
    int idx = blockIdx.x * blockDim.x + threadIdx.x;
    if (idx >= SL * 64) return;
    int pos = idx >> 6;
    int i   = idx & 63;
    double invd = 1.0 / pow(10000.0, (double)i / 64.0);
    float  invf = (float)invd;
    float  ang  = (float)pos * invf;      // fp32 rounding, matches reference
    g_cs[idx] = make_float2((float)cos((double)ang), (float)sin((double)ang));
}

// ---------------- pipelined tf32 NT GEMM: C[m,n] = sum_k A[m,k] * W[n,k] --------
template<int BN, int TU>
__global__ void __launch_bounds__(256, 1) gemm_tf32(
    const float* __restrict__ A0, const float* __restrict__ A1, int split, int M,
    const float* __restrict__ W0, const float* __restrict__ W1, const float* __restrict__ W2,
    float* __restrict__ C0, float* __restrict__ C1, float* __restrict__ C2)
{
    const float* Bw = (blockIdx.z == 0) ? W0 : (blockIdx.z == 1) ? W1 : W2;
    float*       C  = (blockIdx.z == 0) ? C0 : (blockIdx.z == 1) ? C1 : C2;
    const int m0 = blockIdx.y * 128;
    const int n0 = blockIdx.x * BN;

    extern __shared__ unsigned smg[];
    const int ASTR = 132, BSTR = BN + 4;
    const int BOFF = 2 * 32 * ASTR;
#define ASG(bf, k, m) smg[((bf) * 32 + (k)) * ASTR + (m)]
#define BSG(bf, k, n) smg[BOFF + ((bf) * 32 + (k)) * BSTR + (n)]

    const int tid  = threadIdx.x;
    const int wid  = tid >> 5;
    const int lane = tid & 31;
    const int g    = lane >> 2;
    const int tg   = lane & 3;
    const int wm   = (wid >> 2) * 64;
    const int wn   = (wid & 3) * (8 * TU);

    const int am  = tid >> 1;
    const int ak4 = (tid & 1) * 4;
    constexpr int TPR  = 256 / BN;
    constexpr int F4PT = 8 / TPR;
    const int bn  = tid / TPR;
    const int bk4 = (tid % TPR) * F4PT;

    const bool avalid = (m0 + am) < M;
    const float* asrc = avalid
        ? ((m0 + am < split) ? A0 + (size_t)(m0 + am) * HID
                             : A1 + (size_t)(m0 + am - split) * HID)
        : A0;
    const float* bsrc = Bw + (size_t)(n0 + bn) * HID;

    float acc[4][TU][4];
#pragma unroll
    for (int t = 0; t < 4; t++)
#pragma unroll
        for (int u = 0; u < TU; u++)
#pragma unroll
            for (int c = 0; c < 4; c++) acc[t][u][c] = 0.f;

    float4 pa[4], pb[F4PT];

#pragma unroll
    for (int q = 0; q < 4; q++)
        pa[q] = avalid ? *(const float4*)(asrc + (ak4 + q) * 4)
                       : make_float4(0.f, 0.f, 0.f, 0.f);
#pragma unroll
    for (int q = 0; q < F4PT; q++)
        pb[q] = *(const float4*)(bsrc + (bk4 + q) * 4);
#pragma unroll
    for (int q = 0; q < 4; q++) {
        int k = (ak4 + q) * 4;
        ASG(0, k + 0, am) = f2tf(pa[q].x); ASG(0, k + 1, am) = f2tf(pa[q].y);
        ASG(0, k + 2, am) = f2tf(pa[q].z); ASG(0, k + 3, am) = f2tf(pa[q].w);
    }
#pragma unroll
    for (int q = 0; q < F4PT; q++) {
        int k = (bk4 + q) * 4;
        BSG(0, k + 0, bn) = f2tf(pb[q].x); BSG(0, k + 1, bn) = f2tf(pb[q].y);
        BSG(0, k + 2, bn) = f2tf(pb[q].z); BSG(0, k + 3, bn) = f2tf(pb[q].w);
    }
    __syncthreads();

    const int NK = HID / 32;
    for (int t = 0; t < NK; t++) {
        const int cur  = t & 1;
        const bool more = (t + 1 < NK);
        if (more) {
            const int k0 = (t + 1) * 32;
#pragma unroll
            for (int q = 0; q < 4; q++)
                pa[q] = avalid ? *(const float4*)(asrc + k0 + (ak4 + q) * 4)
                               : make_float4(0.f, 0.f, 0.f, 0.f);
#pragma unroll
            for (int q = 0; q < F4PT; q++)
                pb[q] = *(const float4*)(bsrc + k0 + (bk4 + q) * 4);
        }
#pragma unroll
        for (int k8 = 0; k8 < 4; k8++) {
            unsigned a[4][4];
#pragma unroll
            for (int tt = 0; tt < 4; tt++) {
                a[tt][0] = ASG(cur, k8 * 8 + tg,     wm + 16 * tt + g);
                a[tt][1] = ASG(cur, k8 * 8 + tg,     wm + 16 * tt + g + 8);
                a[tt][2] = ASG(cur, k8 * 8 + tg + 4, wm + 16 * tt + g);
                a[tt][3] = ASG(cur, k8 * 8 + tg + 4, wm + 16 * tt + g + 8);
            }
            unsigned b[TU][2];
#pragma unroll
            for (int u = 0; u < TU; u++) {
                b[u][0] = BSG(cur, k8 * 8 + tg,     wn + 8 * u + g);
                b[u][1] = BSG(cur, k8 * 8 + tg + 4, wn + 8 * u + g);
            }
#pragma unroll
            for (int tt = 0; tt < 4; tt++)
#pragma unroll
                for (int u = 0; u < TU; u++)
                    mma_tf32(acc[tt][u], a[tt][0], a[tt][1], a[tt][2], a[tt][3],
                             b[u][0], b[u][1]);
        }
        if (more) {
            const int nxt = cur ^ 1;
#pragma unroll
            for (int q = 0; q < 4; q++) {
                int k = (ak4 + q) * 4;
                ASG(nxt, k + 0, am) = f2tf(pa[q].x); ASG(nxt, k + 1, am) = f2tf(pa[q].y);
                ASG(nxt, k + 2, am) = f2tf(pa[q].z); ASG(nxt, k + 3, am) = f2tf(pa[q].w);
            }
#pragma unroll
            for (int q = 0; q < F4PT; q++) {
                int k = (bk4 + q) * 4;
                BSG(nxt, k + 0, bn) = f2tf(pb[q].x); BSG(nxt, k + 1, bn) = f2tf(pb[q].y);
                BSG(nxt, k + 2, bn) = f2tf(pb[q].z); BSG(nxt, k + 3, bn) = f2tf(pb[q].w);
            }
            __syncthreads();
        }
    }

#pragma unroll
    for (int tt = 0; tt < 4; tt++) {
        int r0 = m0 + wm + 16 * tt + g;
        int r1 = r0 + 8;
#pragma unroll
        for (int u = 0; u < TU; u++) {
            int n = n0 + wn + 8 * u + 2 * tg;
            if (r0 < M) *(float2*)(C + (size_t)r0 * HID + n) = make_float2(acc[tt][u][0], acc[tt][u][1]);
            if (r1 < M) *(float2*)(C + (size_t)r1 * HID + n) = make_float2(acc[tt][u][2], acc[tt][u][3]);
        }
    }
#undef ASG
#undef BSG
}

#define GEMM_SMEM_256 ((2 * 32 * 132 + 2 * 32 * 260) * 4)
#define GEMM_SMEM_128 ((2 * 32 * 132 + 2 * 32 * 132) * 4)

// ---------------- RoPE on Q (also folds 1/sqrt(HD)) ----------------
__global__ void rope_q_kernel(const float* __restrict__ Qp, float* __restrict__ Qr) {
    int idx = blockIdx.x * blockDim.x + threadIdx.x;
    if (idx >= 128 * 128 * 128) return;
    int d  = idx & 127;
    int s  = (idx >> 7) & 127;
    int bh = idx >> 14;
    int b = bh >> 4, h = bh & 15;
    const float* src = Qp + (size_t)(b * 128 + s) * HID + h * 128;
    float v = src[d];
    float p = (d < 64) ? -src[d + 64] : src[d - 64];
    int pos = s + ANC;
    float2 cs = g_cs[pos * 64 + (d & 63)];
    Qr[idx] = (v * cs.x + p * cs.y) * 0.08838834764831845f;
}

// ---------------- fused flash attention (register-prefetch pipelined) ----------
// grid = 128 (one per b,h), 256 threads, 8 warps; warp w owns q rows 16w..16w+15.
// Q fragments live in smem (per-thread-private, written once, LDS.128 reads).
// Next tile's K/V/cs are prefetched into registers during compute.
// smem words: KS 128x36 @0 | VS 32x132 @4608 | PS 8x576 @8832 | QS 256x68 @13440
#define KS(d, j)     sm[(d) * 36 + (j)]
#define VS(j, d)     sm[4608 + (j) * 132 + (d)]
#define PS(w, j, q)  sm[8832 + (w) * 576 + (j) * 18 + (q)]
#define QS_BASE      13440
#define FLASH_SMEM   ((13440 + 256 * 68) * 4)

__global__ void __launch_bounds__(256, 1) flash_attn(
    const float* __restrict__ Qr, const float* __restrict__ Kp,
    const float* __restrict__ Vp, const float* __restrict__ past_k,
    const float* __restrict__ past_v,
    float* __restrict__ kcache, float* __restrict__ vcache,
    float* __restrict__ AO)
{
    extern __shared__ unsigned sm[];
    const int bh = blockIdx.x;
    const int b = bh >> 4, h = bh & 15;
    const int tid  = threadIdx.x;
    const int w    = tid >> 5;
    const int lane = tid & 31;
    const int g    = lane >> 2;
    const int tg   = lane & 3;
    const int qb   = 16 * w;

    const int jj = tid >> 3;          // staged row within tile (0..31)
    const int c0 = (tid & 7) * 8;     // 8 low-d + 8 high-d per thread

    // ---- Q fragments: compute once, park in per-thread smem slots ----
    // QS slot for this thread: 68-float stride (16 float4 frags + pad, conflict-free)
    const int qsb = QS_BASE + ((w * 8 + g) * 4 + tg) * 68;
    {
        const float* q = Qr + (size_t)bh * 128 * 128;
#pragma unroll
        for (int kk = 0; kk < 16; kk++) {
            int d = 8 * kk + tg;
            uint4 fr;
            fr.x = f2tf(q[(qb + g    ) * 128 + d    ]);
            fr.y = f2tf(q[(qb + g + 8) * 128 + d    ]);
            fr.z = f2tf(q[(qb + g    ) * 128 + d + 4]);
            fr.w = f2tf(q[(qb + g + 8) * 128 + d + 4]);
            *(uint4*)&sm[qsb + kk * 4] = fr;
        }
    }

    float Oacc[16][4];
#pragma unroll
    for (int nt = 0; nt < 16; nt++)
#pragma unroll
        for (int c = 0; c < 4; c++) Oacc[nt][c] = 0.f;
    float mrow[2] = {-1e30f, -1e30f};
    float lrow[2] = {0.f, 0.f};

    // ---- prefetch registers for next tile ----
    float  pk[16], pv[16];     // K low/high, V low/high (8+8 each)
    float2 pcs[8];             // cos/sin for d = c0..c0+7 (d+64 shares)
    bool   pvalid = false;
    size_t pcbase = 0;

    auto ldreg_tile = [&](int jt) {
        int jg = jt * 32 + jj;
        pvalid = (jg < SL);
        if (!pvalid) return;
        const float *ksrc, *vsrc;
        if (jg < ANC) {
            ksrc = Kp + (size_t)(1024 + jg) * HID + h * 128;
            vsrc = Vp + (size_t)(1024 + jg) * HID + h * 128;
            pcbase = (size_t)-1;
        } else {
            int cr = jg - ANC;
            pcbase = ((size_t)bh * CTX + cr) * 128;
            if (cr < CTX - SEQ) {
                ksrc = past_k + ((size_t)bh * CTX + cr + SEQ) * 128;
                vsrc = past_v + ((size_t)bh * CTX + cr + SEQ) * 128;
            } else {
                int ss = cr - (CTX - SEQ);
                ksrc = Kp + (size_t)(b * SEQ + ss) * HID + h * 128;
                vsrc = Vp + (size_t)(b * SEQ + ss) * HID + h * 128;
            }
        }
        *(float4*)(pk)      = *(const float4*)(ksrc + c0);
        *(float4*)(pk + 4)  = *(const float4*)(ksrc + c0 + 4);
        *(float4*)(pk + 8)  = *(const float4*)(ksrc + c0 + 64);
        *(float4*)(pk + 12) = *(const float4*)(ksrc + c0 + 68);
        *(float4*)(pv)      = *(const float4*)(vsrc + c0);
        *(float4*)(pv + 4)  = *(const float4*)(vsrc + c0 + 4);
        *(float4*)(pv + 8)  = *(const float4*)(vsrc + c0 + 64);
        *(float4*)(pv + 12) = *(const float4*)(vsrc + c0 + 68);
        const float2* csp = g_cs + (size_t)(jt * 32 + jj) * 64 + c0;
        *(float4*)(&pcs[0]) = *(const float4*)(csp);
        *(float4*)(&pcs[2]) = *(const float4*)(csp + 2);
        *(float4*)(&pcs[4]) = *(const float4*)(csp + 4);
        *(float4*)(&pcs[6]) = *(const float4*)(csp + 6);
    };

    ldreg_tile(0);

    for (int jt = 0; jt < NJT; jt++) {
        // ---- convert phase: prefetch regs -> rope'd tf32 KS / tf32 VS + cache ----
        if (pvalid) {
            if (pcbase != (size_t)-1) {
                *(float4*)(kcache + pcbase + c0)      = *(float4*)(pk);
                *(float4*)(kcache + pcbase + c0 + 4)  = *(float4*)(pk + 4);
                *(float4*)(kcache + pcbase + c0 + 64) = *(float4*)(pk + 8);
                *(float4*)(kcache + pcbase + c0 + 68) = *(float4*)(pk + 12);
                *(float4*)(vcache + pcbase + c0)      = *(float4*)(pv);
                *(float4*)(vcache + pcbase + c0 + 4)  = *(float4*)(pv + 4);
                *(float4*)(vcache + pcbase + c0 + 64) = *(float4*)(pv + 8);
                *(float4*)(vcache + pcbase + c0 + 68) = *(float4*)(pv + 12);
            }
#pragma unroll
            for (int u = 0; u < 8; u++) {
                float2 cs = pcs[u];
                KS(c0 + u,      jj) = f2tf(pk[u]     * cs.x - pk[u + 8] * cs.y);
                KS(c0 + 64 + u, jj) = f2tf(pk[u + 8] * cs.x + pk[u]     * cs.y);
                VS(jj, c0 + u)      = f2tf(pv[u]);
                VS(jj, c0 + 64 + u) = f2tf(pv[u + 8]);
            }
        } else {
#pragma unroll
            for (int u = 0; u < 8; u++) {
                KS(c0 + u, jj) = 0u; KS(c0 + 64 + u, jj) = 0u;
                VS(jj, c0 + u) = 0u; VS(jj, c0 + 64 + u) = 0u;
            }
        }
        __syncthreads();

        // ---- issue next tile's global loads (consumed next iteration) ----
        if (jt + 1 < NJT) ldreg_tile(jt + 1);

        const int j0 = jt * 32;

        // ---- S = Q K^T ----
        float s[4][4];
#pragma unroll
        for (int u = 0; u < 4; u++)
#pragma unroll
            for (int c = 0; c < 4; c++) s[u][c] = 0.f;
#pragma unroll
        for (int kk = 0; kk < 16; kk++) {
            uint4 qa = *(const uint4*)&sm[qsb + kk * 4];
#pragma unroll
            for (int u = 0; u < 4; u++) {
                unsigned b0 = KS(8 * kk + tg,     8 * u + g);
                unsigned b1 = KS(8 * kk + tg + 4, 8 * u + g);
                mma_tf32(s[u], qa.x, qa.y, qa.z, qa.w, b0, b1);
            }
        }

        // ---- mask tail + online softmax ----
#pragma unroll
        for (int u = 0; u < 4; u++) {
            int jl = 8 * u + 2 * tg;
            if (j0 + jl     >= SL) { s[u][0] = -1e30f; s[u][2] = -1e30f; }
            if (j0 + jl + 1 >= SL) { s[u][1] = -1e30f; s[u][3] = -1e30f; }
        }
        float tmax0 = -1e30f, tmax1 = -1e30f;
#pragma unroll
        for (int u = 0; u < 4; u++) {
            tmax0 = fmaxf(tmax0, fmaxf(s[u][0], s[u][1]));
            tmax1 = fmaxf(tmax1, fmaxf(s[u][2], s[u][3]));
        }
        tmax0 = fmaxf(tmax0, __shfl_xor_sync(0xffffffff, tmax0, 1));
        tmax0 = fmaxf(tmax0, __shfl_xor_sync(0xffffffff, tmax0, 2));
        tmax1 = fmaxf(tmax1, __shfl_xor_sync(0xffffffff, tmax1, 1));
        tmax1 = fmaxf(tmax1, __shfl_xor_sync(0xffffffff, tmax1, 2));
        float mn0 = fmaxf(mrow[0], tmax0);
        float mn1 = fmaxf(mrow[1], tmax1);
        float al0 = __expf(mrow[0] - mn0);
        float al1 = __expf(mrow[1] - mn1);
        mrow[0] = mn0; mrow[1] = mn1;

        float rs0 = 0.f, rs1 = 0.f;
#pragma unroll
        for (int u = 0; u < 4; u++) {
            s[u][0] = __expf(s[u][0] - mn0);
            s[u][1] = __expf(s[u][1] - mn0);
            s[u][2] = __expf(s[u][2] - mn1);
            s[u][3] = __expf(s[u][3] - mn1);
            rs0 += s[u][0] + s[u][1];
            rs1 += s[u][2] + s[u][3];
        }
        rs0 += __shfl_xor_sync(0xffffffff, rs0, 1);
        rs0 += __shfl_xor_sync(0xffffffff, rs0, 2);
        rs1 += __shfl_xor_sync(0xffffffff, rs1, 1);
        rs1 += __shfl_xor_sync(0xffffffff, rs1, 2);
        lrow[0] = lrow[0] * al0 + rs0;
        lrow[1] = lrow[1] * al1 + rs1;

#pragma unroll
        for (int nt = 0; nt < 16; nt++) {
            Oacc[nt][0] *= al0; Oacc[nt][1] *= al0;
            Oacc[nt][2] *= al1; Oacc[nt][3] *= al1;
        }

        // ---- P -> smem (per-warp) ----
#pragma unroll
        for (int u = 0; u < 4; u++) {
            int jl = 8 * u + 2 * tg;
            PS(w, jl,     g    ) = f2tf(s[u][0]);
            PS(w, jl + 1, g    ) = f2tf(s[u][1]);
            PS(w, jl,     g + 8) = f2tf(s[u][2]);
            PS(w, jl + 1, g + 8) = f2tf(s[u][3]);
        }
        __syncwarp();

        // ---- O += P V ----
#pragma unroll
        for (int kk = 0; kk < 4; kk++) {
            unsigned a0 = PS(w, 8 * kk + tg,     g);
            unsigned a1 = PS(w, 8 * kk + tg,     g + 8);
            unsigned a2 = PS(w, 8 * kk + tg + 4, g);
            unsigned a3 = PS(w, 8 * kk + tg + 4, g + 8);
#pragma unroll
            for (int nt = 0; nt < 16; nt++) {
                unsigned b0 = VS(8 * kk + tg,     8 * nt + g);
                unsigned b1 = VS(8 * kk + tg + 4, 8 * nt + g);
                mma_tf32(Oacc[nt], a0, a1, a2, a3, b0, b1);
            }
        }
        __syncthreads();
    }

    // ---- epilogue ----
    float inv0 = 1.0f / lrow[0];
    float inv1 = 1.0f / lrow[1];
    int r0 = b * 128 + qb + g;
    int r1 = r0 + 8;
#pragma unroll
    for (int nt = 0; nt < 16; nt++) {
        int d = h * 128 + 8 * nt + 2 * tg;
        *(float2*)(AO + (size_t)r0 * HID + d) = make_float2(Oacc[nt][0] * inv0, Oacc[nt][1] * inv0);
        *(float2*)(AO + (size_t)r1 * HID + d) = make_float2(Oacc[nt][2] * inv1, Oacc[nt][3] * inv1);
    }
}

// ---------------- launch ----------------
extern "C" void kernel_launch(void* const* d_in, const int* in_sizes, int n_in,
                              void* d_out, int out_size)
{
    const float* x      = (const float*)d_in[0];
    const float* past_k = (const float*)d_in[2];
    const float* past_v = (const float*)d_in[3];
    const float* anchor = (const float*)d_in[4];
    const float* Wq     = (const float*)d_in[5];
    const float* Wk     = (const float*)d_in[6];
    const float* Wv     = (const float*)d_in[7];
    const float* Wo     = (const float*)d_in[8];

    float* out    = (float*)d_out;
    float* kcache = out + (size_t)NBATCH * SEQ * HID;
    float* vcache = kcache + (size_t)NBATCH * NHEAD * CTX * HD;

    float *Qp, *Kp, *Vp, *Qr, *AO;
    cudaGetSymbolAddress((void**)&Qp, g_Qp);
    cudaGetSymbolAddress((void**)&Kp, g_Kp);
    cudaGetSymbolAddress((void**)&Vp, g_Vp);
    cudaGetSymbolAddress((void**)&Qr, g_Qr);
    cudaGetSymbolAddress((void**)&AO, g_AO);

    cudaFuncSetAttribute(gemm_tf32<256, 8>, cudaFuncAttributeMaxDynamicSharedMemorySize,
                         GEMM_SMEM_256);
    cudaFuncSetAttribute(gemm_tf32<128, 4>, cudaFuncAttributeMaxDynamicSharedMemorySize,
                         GEMM_SMEM_128);
    cudaFuncSetAttribute(flash_attn, cudaFuncAttributeMaxDynamicSharedMemorySize,
                         FLASH_SMEM);

    // 1) QKV projections
    gemm_tf32<256, 8><<<dim3(8, 9, 3), 256, GEMM_SMEM_256>>>(
        x, anchor, 1024, MROWS, Wq, Wk, Wv, Qp, Kp, Vp);

    // 2) RoPE table + Q rope
    rope_table_kernel<<<(SL * 64 + 255) / 256, 256>>>();
    rope_q_kernel<<<(128 * 128 * 128) / 256, 256>>>(Qp, Qr);

    // 3) fused attention (register-prefetch pipelined; assembles caches)
    flash_attn<<<128, 256, FLASH_SMEM>>>(Qr, Kp, Vp, past_k, past_v,
                                         kcache, vcache, AO);

    // 4) output projection
    gemm_tf32<128, 4><<<dim3(16, 8, 1), 256, GEMM_SMEM_128>>>(
        AO, AO, 1024, 1024, Wo, Wo, Wo, out, out, out);
}